// round 1
// baseline (speedup 1.0000x reference)
#include <cuda_runtime.h>

// SPDUnVectorize: x[B, L] packed upper triangle (row-major, incl. diag) ->
// out[B, n, n] symmetric. B=1024, n=256, L=n(n+1)/2=32896.
//
// off(r) = r*n - r*(r-1)/2 ; idx(r,c) = off(r) + (c-r) for c>=r.

#define NMAT   256
#define L_IN   32896
#define BATCH  1024
#define TILE   32
#define NTROW  (NMAT / TILE)          // 8 tile rows
#define NTILES (NTROW * (NTROW + 1) / 2)  // 36 upper-triangle tiles

__device__ __forceinline__ int tri_off(int r) {
    // offset of row r's first packed element
    return r * NMAT - (r * (r - 1)) / 2;
}

__global__ __launch_bounds__(256, 8)
void spd_unvec_kernel(const float* __restrict__ in, float* __restrict__ out) {
    __shared__ float s[TILE][TILE + 1];

    const int b = blockIdx.y;
    int t = blockIdx.x;

    // map t in [0,36) -> (ti, tj) with ti <= tj
    int ti = 0;
    int rem = NTROW;
    while (t >= rem) { t -= rem; rem--; ti++; }
    const int tj = ti + t;

    const int tx = threadIdx.x;   // 0..31
    const int ty = threadIdx.y;   // 0..7

    const float* __restrict__ inb  = in  + (size_t)b * L_IN;
    float*       __restrict__ outb = out + (size_t)b * (NMAT * NMAT);

    if (ti == tj) {
        // Diagonal tile: load upper half (c >= r), mirror in smem, one store.
        #pragma unroll
        for (int k = 0; k < 4; k++) {
            const int ry = ty + k * 8;
            const int r  = ti * TILE + ry;
            const int c  = ti * TILE + tx;
            if (tx >= ry) {
                s[ry][tx] = inb[tri_off(r) + (c - r)];
            }
        }
        __syncthreads();
        #pragma unroll
        for (int k = 0; k < 4; k++) {
            const int ry = ty + k * 8;
            const int r  = ti * TILE + ry;
            const int c  = ti * TILE + tx;
            const float v = (tx >= ry) ? s[ry][tx] : s[tx][ry];
            outb[r * NMAT + c] = v;   // coalesced
        }
    } else {
        // Off-diagonal tile (ti < tj): every (r,c) has c > r.
        // Load is coalesced: packed row segment is contiguous in the input.
        #pragma unroll
        for (int k = 0; k < 4; k++) {
            const int ry = ty + k * 8;
            const int r  = ti * TILE + ry;
            const int c  = tj * TILE + tx;
            const float v = inb[tri_off(r) + (c - r)];
            s[ry][tx] = v;
            outb[r * NMAT + c] = v;   // coalesced store of the upper tile
        }
        __syncthreads();
        // Transposed mirror tile, coalesced via smem.
        #pragma unroll
        for (int k = 0; k < 4; k++) {
            const int ry = ty + k * 8;
            const int r2 = tj * TILE + ry;    // row in mirror tile
            const int c2 = ti * TILE + tx;    // col in mirror tile
            outb[r2 * NMAT + c2] = s[tx][ry];
        }
    }
}

extern "C" void kernel_launch(void* const* d_in, const int* in_sizes, int n_in,
                              void* d_out, int out_size) {
    const float* in = (const float*)d_in[0];
    float* out = (float*)d_out;
    dim3 grid(NTILES, BATCH);
    dim3 block(TILE, 8);
    spd_unvec_kernel<<<grid, block>>>(in, out);
}

// round 2
// speedup vs baseline: 1.0067x; 1.0067x over previous
#include <cuda_runtime.h>

// SPDUnVectorize: x[B, L] packed upper triangle (row-major, incl. diag) ->
// out[B, n, n] symmetric. B=1024, n=256, L=n(n+1)/2=32896.
//
// off(r) = r*n - r*(r-1)/2 ; idx(r,c) = off(r) + (c-r) for c>=r.

#define NMAT   256
#define L_IN   32896
#define BATCH  1024
#define TILE   32
#define NTROW  (NMAT / TILE)               // 8 tile rows
#define NTILES (NTROW * (NTROW + 1) / 2)   // 36 upper-triangle tiles

__device__ __forceinline__ int tri_off(int r) {
    return r * NMAT - (r * (r - 1)) / 2;
}

__global__ __launch_bounds__(256, 8)
void spd_unvec_kernel(const float* __restrict__ in, float* __restrict__ out) {
    __shared__ float s[TILE][TILE + 1];

    const int b = blockIdx.y;
    int t = blockIdx.x;

    // map t in [0,36) -> (ti, tj) with ti <= tj
    int ti = 0;
    int rem = NTROW;
    while (t >= rem) { t -= rem; rem--; ti++; }
    const int tj = ti + t;

    const int tid = threadIdx.x;        // 0..255
    const int row = tid >> 3;           // 0..31  (row within tile)
    const int qc  = (tid & 7) << 2;     // 0,4,...,28 (float4 col within tile)

    const float* __restrict__ inb  = in  + (size_t)b * L_IN;
    float*       __restrict__ outb = out + (size_t)b * (NMAT * NMAT);

    const int r    = ti * TILE + row;                 // global matrix row (upper tile)
    const int base = tri_off(r) - r + tj * TILE;      // packed index of col (tj*TILE + 0)

    if (ti == tj) {
        // Diagonal tile: load upper half (c >= row within tile), mirror via smem.
        #pragma unroll
        for (int k = 0; k < 4; k++) {
            const int c = qc + k;
            if (c >= row) s[row][c] = inb[base + c];
        }
        __syncthreads();
        float4 v;
        v.x = (qc + 0 >= row) ? s[row][qc + 0] : s[qc + 0][row];
        v.y = (qc + 1 >= row) ? s[row][qc + 1] : s[qc + 1][row];
        v.z = (qc + 2 >= row) ? s[row][qc + 2] : s[qc + 2][row];
        v.w = (qc + 3 >= row) ? s[row][qc + 3] : s[qc + 3][row];
        *reinterpret_cast<float4*>(&outb[r * NMAT + ti * TILE + qc]) = v;
    } else {
        // Off-diagonal tile (ti < tj): all elements have c > r.
        float4 v;
        v.x = inb[base + qc + 0];
        v.y = inb[base + qc + 1];
        v.z = inb[base + qc + 2];
        v.w = inb[base + qc + 3];

        s[row][qc + 0] = v.x;
        s[row][qc + 1] = v.y;
        s[row][qc + 2] = v.z;
        s[row][qc + 3] = v.w;

        // Upper tile store: 128-bit, coalesced.
        *reinterpret_cast<float4*>(&outb[r * NMAT + tj * TILE + qc]) = v;

        __syncthreads();

        // Transposed mirror tile: 128-bit, coalesced; smem reads conflict-free.
        float4 w;
        w.x = s[qc + 0][row];
        w.y = s[qc + 1][row];
        w.z = s[qc + 2][row];
        w.w = s[qc + 3][row];
        const int r2 = tj * TILE + row;
        *reinterpret_cast<float4*>(&outb[r2 * NMAT + ti * TILE + qc]) = w;
    }
}

extern "C" void kernel_launch(void* const* d_in, const int* in_sizes, int n_in,
                              void* d_out, int out_size) {
    const float* in = (const float*)d_in[0];
    float* out = (float*)d_out;
    dim3 grid(NTILES, BATCH);
    dim3 block(256);
    spd_unvec_kernel<<<grid, block>>>(in, out);
}